// round 8
// baseline (speedup 1.0000x reference)
#include <cuda_runtime.h>
#include <cuda_bf16.h>
#include <cstdint>

// Problem constants (fixed by the reference):
//   T=20 timesteps, G=1024 groups, P=64 peds/group, THR=0.25
//   out[g*P*P*T + (i*P+j)*T + t] = relu(THR - sqrt(dist2 + (i==j)))
// trajectory_relative and seq_start_end are unused (uniform contiguous groups).

#define TT 20
#define GG 1024
#define PP 64
#define THRC 0.25f
#define NTHREADS 160          // 32 j_lo * 5 t-chunks; each thread owns 2 j's
#define ISPLIT 2              // blocks per group along i
#define IPB (PP / ISPLIT)     // 32 i-iterations per block

// smem tile: pedestrian-major, row padded to 22 float2 = 176 B (16B multiple)
#define TPAD 22

__device__ __forceinline__ float sqrt_approx(float x) {
    float r;
    asm("sqrt.approx.f32 %0, %1;" : "=f"(r) : "f"(x));
    return r;
}

// Cost for 4 timesteps of one (i,j) pair; diag=1.0f on the diagonal makes
// relu(THR - sqrt(0+1)) == 0 exactly (matches the reference's identity add).
__device__ __forceinline__ float4 pair_cost(const float4& a01, const float4& a23,
                                            const float4& b01, const float4& b23,
                                            float diag) {
    float dx0 = a01.x - b01.x, dy0 = a01.y - b01.y;
    float dx1 = a01.z - b01.z, dy1 = a01.w - b01.w;
    float dx2 = a23.x - b23.x, dy2 = a23.y - b23.y;
    float dx3 = a23.z - b23.z, dy3 = a23.w - b23.w;

    float s0 = fmaf(dy0, dy0, fmaf(dx0, dx0, diag));
    float s1 = fmaf(dy1, dy1, fmaf(dx1, dx1, diag));
    float s2 = fmaf(dy2, dy2, fmaf(dx2, dx2, diag));
    float s3 = fmaf(dy3, dy3, fmaf(dx3, dx3, diag));

    float4 v;
    v.x = fmaxf(0.0f, THRC - sqrt_approx(s0));
    v.y = fmaxf(0.0f, THRC - sqrt_approx(s1));
    v.z = fmaxf(0.0f, THRC - sqrt_approx(s2));
    v.w = fmaxf(0.0f, THRC - sqrt_approx(s3));
    return v;
}

__global__ __launch_bounds__(NTHREADS, 10)
void traj_cost_kernel(const float2* __restrict__ traj, float* __restrict__ out) {
    const int g = blockIdx.y;
    const int i0 = blockIdx.x * IPB;

    __shared__ float2 xs[PP][TPAD];   // [pedestrian][timestep]

    // Load group slab, transposing t-major global -> p-major smem.
    const float2* gsrc = traj + (size_t)g * PP;
    #pragma unroll
    for (int idx = threadIdx.x; idx < TT * PP; idx += NTHREADS) {
        int t = idx >> 6;          // /64
        int p = idx & (PP - 1);    // %64
        xs[p][t] = gsrc[(size_t)t * (GG * PP) + p];
    }
    __syncthreads();

    // Thread identity: tid = j_lo*5 + m; this thread owns j_lo and j_lo+32.
    const int j_lo = threadIdx.x / 5;
    const int m    = threadIdx.x - j_lo * 5;
    const int t0   = m << 2;
    const int j_hi = j_lo + 32;

    // Both b operands register-resident for all i (16 regs).
    const float4* bpA = reinterpret_cast<const float4*>(&xs[j_lo][t0]);
    const float4 bA01 = bpA[0];
    const float4 bA23 = bpA[1];
    const float4* bpB = reinterpret_cast<const float4*>(&xs[j_hi][t0]);
    const float4 bB01 = bpB[0];
    const float4 bB23 = bpB[1];

    // Store base: out[g*P*P*T + i*P*T + j*T + t0].
    // Lanes are consecutive tid -> consecutive 16B slots: each STG.128 is a
    // 512 B contiguous warp store; j_hi half is another contiguous span.
    float* goutA = out + (size_t)g * (PP * PP * TT) + (size_t)j_lo * TT + t0
                 + (size_t)i0 * (PP * TT);

    #pragma unroll 2
    for (int ii = 0; ii < IPB; ii++) {
        const int i = i0 + ii;

        // One shared 'a' load feeds both j outputs (2 LDS.128 per 2 STG.128).
        const float4* ap = reinterpret_cast<const float4*>(&xs[i][t0]);
        float4 a01 = ap[0];
        float4 a23 = ap[1];

        const float diagA = (i == j_lo) ? 1.0f : 0.0f;
        const float diagB = (i == j_hi) ? 1.0f : 0.0f;

        float4 vA = pair_cost(a01, a23, bA01, bA23, diagA);
        float4 vB = pair_cost(a01, a23, bB01, bB23, diagB);

        float* row = goutA + (size_t)ii * (PP * TT);
        __stcs(reinterpret_cast<float4*>(row), vA);
        __stcs(reinterpret_cast<float4*>(row + 32 * TT), vB);
    }
}

extern "C" void kernel_launch(void* const* d_in, const int* in_sizes, int n_in,
                              void* d_out, int out_size) {
    const float2* traj = (const float2*)d_in[0];  // trajectory (T, G*P, 2)
    float* out = (float*)d_out;                    // (G*P*P*T) fp32

    dim3 grid(ISPLIT, GG);
    traj_cost_kernel<<<grid, NTHREADS>>>(traj, out);
}

// round 9
// speedup vs baseline: 1.0091x; 1.0091x over previous
#include <cuda_runtime.h>
#include <cuda_bf16.h>
#include <cstdint>

// Problem constants (fixed by the reference):
//   T=20 timesteps, G=1024 groups, P=64 peds/group, THR=0.25
//   out[g*P*P*T + (i*P+j)*T + t] = relu(THR - sqrt(dist2 + (i==j)))
// trajectory_relative and seq_start_end are unused (uniform contiguous groups).

#define TT 20
#define GG 1024
#define PP 64
#define THRC 0.25f
#define NTHREADS 160          // 32 j_lo * 5 t-chunks; each thread owns 2 j's
#define IPB PP                // one block per group: all 64 i-iterations

// smem tile: pedestrian-major, row padded to 22 float2 = 176 B (16B multiple)
#define TPAD 22

__device__ __forceinline__ uint64_t f32x2_add(uint64_t a, uint64_t b) {
    uint64_t r;
    asm("add.rn.f32x2 %0, %1, %2;" : "=l"(r) : "l"(a), "l"(b));
    return r;
}
__device__ __forceinline__ uint64_t f32x2_mul(uint64_t a, uint64_t b) {
    uint64_t r;
    asm("mul.rn.f32x2 %0, %1, %2;" : "=l"(r) : "l"(a), "l"(b));
    return r;
}
__device__ __forceinline__ float2 unpack_f32x2(uint64_t v) {
    float lo, hi;
    asm("mov.b64 {%0, %1}, %2;" : "=f"(lo), "=f"(hi) : "l"(v));
    return make_float2(lo, hi);
}
__device__ __forceinline__ uint64_t pack_f32x2(float lo, float hi) {
    uint64_t r;
    asm("mov.b64 %0, {%1, %2};" : "=l"(r) : "f"(lo), "f"(hi));
    return r;
}
__device__ __forceinline__ float sqrt_approx(float x) {
    float r;
    asm("sqrt.approx.f32 %0, %1;" : "=f"(r) : "f"(x));
    return r;
}

struct NegB { uint64_t n0, n1, n2, n3; };

__device__ __forceinline__ NegB load_negb(const float2 (*xs)[TPAD], int j, int t0) {
    const float4* bp = reinterpret_cast<const float4*>(&xs[j][t0]);
    float4 b01 = bp[0];
    float4 b23 = bp[1];
    NegB nb;
    nb.n0 = pack_f32x2(-b01.x, -b01.y);
    nb.n1 = pack_f32x2(-b01.z, -b01.w);
    nb.n2 = pack_f32x2(-b23.x, -b23.y);
    nb.n3 = pack_f32x2(-b23.z, -b23.w);
    return nb;
}

// Cost for 4 timesteps of one (i,j) pair; diag=1.0f on the diagonal makes
// relu(THR - sqrt(0+1)) == 0 exactly (matches the reference's identity add).
__device__ __forceinline__ float4 pair_cost(const ulonglong2& a01, const ulonglong2& a23,
                                            const NegB& nb, float diag) {
    uint64_t d0 = f32x2_add(a01.x, nb.n0);
    uint64_t d1 = f32x2_add(a01.y, nb.n1);
    uint64_t d2 = f32x2_add(a23.x, nb.n2);
    uint64_t d3 = f32x2_add(a23.y, nb.n3);

    uint64_t s0 = f32x2_mul(d0, d0);
    uint64_t s1 = f32x2_mul(d1, d1);
    uint64_t s2 = f32x2_mul(d2, d2);
    uint64_t s3 = f32x2_mul(d3, d3);

    float2 q0 = unpack_f32x2(s0);
    float2 q1 = unpack_f32x2(s1);
    float2 q2 = unpack_f32x2(s2);
    float2 q3 = unpack_f32x2(s3);

    float4 v;
    v.x = fmaxf(0.0f, THRC - sqrt_approx(q0.x + q0.y + diag));
    v.y = fmaxf(0.0f, THRC - sqrt_approx(q1.x + q1.y + diag));
    v.z = fmaxf(0.0f, THRC - sqrt_approx(q2.x + q2.y + diag));
    v.w = fmaxf(0.0f, THRC - sqrt_approx(q3.x + q3.y + diag));
    return v;
}

__global__ __launch_bounds__(NTHREADS)
void traj_cost_kernel(const float2* __restrict__ traj, float* __restrict__ out) {
    const int g = blockIdx.x;     // one block per group -> single wave, no tail

    __shared__ float2 xs[PP][TPAD];   // [pedestrian][timestep]

    // Load group slab, transposing t-major global -> p-major smem.
    const float2* gsrc = traj + (size_t)g * PP;
    #pragma unroll
    for (int idx = threadIdx.x; idx < TT * PP; idx += NTHREADS) {
        int t = idx >> 6;          // /64
        int p = idx & (PP - 1);    // %64
        xs[p][t] = gsrc[(size_t)t * (GG * PP) + p];
    }
    __syncthreads();

    // Thread identity: tid = j_lo*5 + m; this thread owns j_lo and j_lo+32.
    const int j_lo = threadIdx.x / 5;
    const int m    = threadIdx.x - j_lo * 5;
    const int t0   = m << 2;
    const int j_hi = j_lo + 32;

    // Both b operands register-resident (negated, f32x2-packed) for all i.
    const NegB nbA = load_negb(xs, j_lo, t0);
    const NegB nbB = load_negb(xs, j_hi, t0);

    // Store base: out[g*P*P*T + i*P*T + j*T + t0].
    // Lanes are consecutive tid -> consecutive 16B slots: each STG.128 is a
    // 512 B contiguous warp store; j_hi half is another contiguous span.
    float* goutA = out + (size_t)g * (PP * PP * TT) + (size_t)j_lo * TT + t0;

    #pragma unroll 2
    for (int i = 0; i < IPB; i++) {
        // One shared 'a' load feeds both j outputs (2 LDS.128 per 2 STG.128).
        const ulonglong2* ap = reinterpret_cast<const ulonglong2*>(&xs[i][t0]);
        ulonglong2 a01 = ap[0];
        ulonglong2 a23 = ap[1];

        const float diagA = (i == j_lo) ? 1.0f : 0.0f;
        const float diagB = (i == j_hi) ? 1.0f : 0.0f;

        float4 vA = pair_cost(a01, a23, nbA, diagA);
        float4 vB = pair_cost(a01, a23, nbB, diagB);

        float* row = goutA + (size_t)i * (PP * TT);
        __stcs(reinterpret_cast<float4*>(row), vA);
        __stcs(reinterpret_cast<float4*>(row + 32 * TT), vB);
    }
}

extern "C" void kernel_launch(void* const* d_in, const int* in_sizes, int n_in,
                              void* d_out, int out_size) {
    const float2* traj = (const float2*)d_in[0];  // trajectory (T, G*P, 2)
    float* out = (float*)d_out;                    // (G*P*P*T) fp32

    traj_cost_kernel<<<GG, NTHREADS>>>(traj, out);
}

// round 10
// speedup vs baseline: 1.0803x; 1.0706x over previous
#include <cuda_runtime.h>
#include <cuda_bf16.h>
#include <cstdint>

// Problem constants (fixed by the reference):
//   T=20 timesteps, G=1024 groups, P=64 peds/group, THR=0.25
//   out[g*P*P*T + (i*P+j)*T + t] = relu(THR - sqrt(dist2 + (i==j)))
// trajectory_relative and seq_start_end are unused (uniform contiguous groups).

#define TT 20
#define GG 1024
#define PP 64
#define THRC 0.25f
#define NTHREADS 160          // 32 j_lo * 5 t-chunks; each thread owns 2 j's
#define ISPLIT 2              // blocks per group along i
#define IPB (PP / ISPLIT)     // 32 i-iterations per block

// smem tile: pedestrian-major, row padded to 22 float2 = 176 B (16B multiple)
#define TPAD 22

__device__ __forceinline__ uint64_t f32x2_add(uint64_t a, uint64_t b) {
    uint64_t r;
    asm("add.rn.f32x2 %0, %1, %2;" : "=l"(r) : "l"(a), "l"(b));
    return r;
}
__device__ __forceinline__ uint64_t f32x2_mul(uint64_t a, uint64_t b) {
    uint64_t r;
    asm("mul.rn.f32x2 %0, %1, %2;" : "=l"(r) : "l"(a), "l"(b));
    return r;
}
__device__ __forceinline__ float2 unpack_f32x2(uint64_t v) {
    float lo, hi;
    asm("mov.b64 {%0, %1}, %2;" : "=f"(lo), "=f"(hi) : "l"(v));
    return make_float2(lo, hi);
}
__device__ __forceinline__ uint64_t pack_f32x2(float lo, float hi) {
    uint64_t r;
    asm("mov.b64 %0, {%1, %2};" : "=l"(r) : "f"(lo), "f"(hi));
    return r;
}
__device__ __forceinline__ float sqrt_approx(float x) {
    float r;
    asm("sqrt.approx.f32 %0, %1;" : "=f"(r) : "f"(x));
    return r;
}

struct NegB { uint64_t n0, n1, n2, n3; };

__device__ __forceinline__ NegB load_negb(const float2 (*xs)[TPAD], int j, int t0) {
    const float4* bp = reinterpret_cast<const float4*>(&xs[j][t0]);
    float4 b01 = bp[0];
    float4 b23 = bp[1];
    NegB nb;
    nb.n0 = pack_f32x2(-b01.x, -b01.y);
    nb.n1 = pack_f32x2(-b01.z, -b01.w);
    nb.n2 = pack_f32x2(-b23.x, -b23.y);
    nb.n3 = pack_f32x2(-b23.z, -b23.w);
    return nb;
}

// Cost for 4 timesteps of one (i,j) pair; diag=1.0f on the diagonal makes
// relu(THR - sqrt(0+1)) == 0 exactly (matches the reference's identity add).
__device__ __forceinline__ float4 pair_cost(const ulonglong2& a01, const ulonglong2& a23,
                                            const NegB& nb, float diag) {
    uint64_t d0 = f32x2_add(a01.x, nb.n0);
    uint64_t d1 = f32x2_add(a01.y, nb.n1);
    uint64_t d2 = f32x2_add(a23.x, nb.n2);
    uint64_t d3 = f32x2_add(a23.y, nb.n3);

    uint64_t s0 = f32x2_mul(d0, d0);
    uint64_t s1 = f32x2_mul(d1, d1);
    uint64_t s2 = f32x2_mul(d2, d2);
    uint64_t s3 = f32x2_mul(d3, d3);

    float2 q0 = unpack_f32x2(s0);
    float2 q1 = unpack_f32x2(s1);
    float2 q2 = unpack_f32x2(s2);
    float2 q3 = unpack_f32x2(s3);

    float4 v;
    v.x = fmaxf(0.0f, THRC - sqrt_approx(q0.x + q0.y + diag));
    v.y = fmaxf(0.0f, THRC - sqrt_approx(q1.x + q1.y + diag));
    v.z = fmaxf(0.0f, THRC - sqrt_approx(q2.x + q2.y + diag));
    v.w = fmaxf(0.0f, THRC - sqrt_approx(q3.x + q3.y + diag));
    return v;
}

__global__ __launch_bounds__(NTHREADS)
void traj_cost_kernel(const float2* __restrict__ traj, float* __restrict__ out) {
    const int g = blockIdx.y;
    const int i0 = blockIdx.x * IPB;

    __shared__ float2 xs[PP][TPAD];   // [pedestrian][timestep]

    // Load group slab, transposing t-major global -> p-major smem.
    const float2* gsrc = traj + (size_t)g * PP;
    #pragma unroll
    for (int idx = threadIdx.x; idx < TT * PP; idx += NTHREADS) {
        int t = idx >> 6;          // /64
        int p = idx & (PP - 1);    // %64
        xs[p][t] = gsrc[(size_t)t * (GG * PP) + p];
    }
    __syncthreads();

    // Thread identity: tid = j_lo*5 + m; this thread owns j_lo and j_lo+32.
    const int j_lo = threadIdx.x / 5;
    const int m    = threadIdx.x - j_lo * 5;
    const int t0   = m << 2;
    const int j_hi = j_lo + 32;

    // Both b operands register-resident (negated, f32x2-packed) for all i.
    const NegB nbA = load_negb(xs, j_lo, t0);
    const NegB nbB = load_negb(xs, j_hi, t0);

    // Store base: out[g*P*P*T + i*P*T + j*T + t0].
    // Lanes are consecutive tid -> consecutive 16B slots: each STG.128 is a
    // 512 B contiguous warp store; j_hi half is another contiguous span.
    float* goutA = out + (size_t)g * (PP * PP * TT) + (size_t)j_lo * TT + t0
                 + (size_t)i0 * (PP * TT);

    // Deep unroll: front-batch LDS and emit dense back-to-back STG.128
    // bursts to maximize outstanding stores per warp.
    #pragma unroll 8
    for (int ii = 0; ii < IPB; ii++) {
        const int i = i0 + ii;

        // One shared 'a' load feeds both j outputs (2 LDS.128 per 2 STG.128).
        const ulonglong2* ap = reinterpret_cast<const ulonglong2*>(&xs[i][t0]);
        ulonglong2 a01 = ap[0];
        ulonglong2 a23 = ap[1];

        const float diagA = (i == j_lo) ? 1.0f : 0.0f;
        const float diagB = (i == j_hi) ? 1.0f : 0.0f;

        float4 vA = pair_cost(a01, a23, nbA, diagA);
        float4 vB = pair_cost(a01, a23, nbB, diagB);

        float* row = goutA + (size_t)ii * (PP * TT);
        __stcs(reinterpret_cast<float4*>(row), vA);
        __stcs(reinterpret_cast<float4*>(row + 32 * TT), vB);
    }
}

extern "C" void kernel_launch(void* const* d_in, const int* in_sizes, int n_in,
                              void* d_out, int out_size) {
    const float2* traj = (const float2*)d_in[0];  // trajectory (T, G*P, 2)
    float* out = (float*)d_out;                    // (G*P*P*T) fp32

    dim3 grid(ISPLIT, GG);
    traj_cost_kernel<<<grid, NTHREADS>>>(traj, out);
}

// round 11
// speedup vs baseline: 1.1155x; 1.0326x over previous
#include <cuda_runtime.h>
#include <cuda_bf16.h>
#include <cstdint>

// Problem constants (fixed by the reference):
//   T=20 timesteps, G=1024 groups, P=64 peds/group, THR=0.25
//   out[g*P*P*T + (i*P+j)*T + t] = relu(THR - sqrt(dist2 + (i==j)))
// trajectory_relative and seq_start_end are unused (uniform contiguous groups).
//
// Structure (settled over R1-R10):
//  - per-group tile in smem, pedestrian-major (LDS.128-friendly)
//  - thread = (j, t-chunk); operand b_j register-resident (f32x2, negated)
//  - sweep i; 1 LDS.128-pair + 1 STG.128 per output float4
//  - stores: warp = 512 B contiguous, streaming (.cs)
//  - branchless diagonal via +1 under the sqrt (reference's own identity trick)
// The kernel sits at the effective HBM write-stream ceiling (~6 TB/s produced).

#define TT 20
#define GG 1024
#define PP 64
#define THRC 0.25f
#define NTHREADS 320          // 64 j * 5 t-chunks
#define ISPLIT 2              // blocks per group along i
#define IPB (PP / ISPLIT)     // 32 i-iterations per block

// smem tile: pedestrian-major, row padded to 22 float2 = 176 B (16B multiple)
#define TPAD 22

__device__ __forceinline__ uint64_t f32x2_add(uint64_t a, uint64_t b) {
    uint64_t r;
    asm("add.rn.f32x2 %0, %1, %2;" : "=l"(r) : "l"(a), "l"(b));
    return r;
}
__device__ __forceinline__ uint64_t f32x2_mul(uint64_t a, uint64_t b) {
    uint64_t r;
    asm("mul.rn.f32x2 %0, %1, %2;" : "=l"(r) : "l"(a), "l"(b));
    return r;
}
__device__ __forceinline__ float2 unpack_f32x2(uint64_t v) {
    float lo, hi;
    asm("mov.b64 {%0, %1}, %2;" : "=f"(lo), "=f"(hi) : "l"(v));
    return make_float2(lo, hi);
}
__device__ __forceinline__ uint64_t pack_f32x2(float lo, float hi) {
    uint64_t r;
    asm("mov.b64 %0, {%1, %2};" : "=l"(r) : "f"(lo), "f"(hi));
    return r;
}
__device__ __forceinline__ float sqrt_approx(float x) {
    float r;
    asm("sqrt.approx.f32 %0, %1;" : "=f"(r) : "f"(x));
    return r;
}

__global__ __launch_bounds__(NTHREADS)
void traj_cost_kernel(const float2* __restrict__ traj, float* __restrict__ out) {
    const int g = blockIdx.y;
    const int i0 = blockIdx.x * IPB;

    __shared__ float2 xs[PP][TPAD];   // [pedestrian][timestep]

    // Load group slab, transposing t-major global -> p-major smem.
    const float2* gsrc = traj + (size_t)g * PP;
    #pragma unroll
    for (int idx = threadIdx.x; idx < TT * PP; idx += NTHREADS) {
        int t = idx >> 6;          // /64
        int p = idx & (PP - 1);    // %64
        xs[p][t] = gsrc[(size_t)t * (GG * PP) + p];
    }
    __syncthreads();

    // Thread identity: tid = j*5 + m  (j = other pedestrian, m = t-chunk)
    const int j  = threadIdx.x / 5;
    const int m  = threadIdx.x - j * 5;
    const int t0 = m << 2;

    // Operand b_j: this thread's 4 timesteps, negated and packed as f32x2,
    // kept in registers for all i.
    const float4* bp = reinterpret_cast<const float4*>(&xs[j][t0]);
    const float4 b01 = bp[0];   // (x_t0, y_t0, x_t0+1, y_t0+1)
    const float4 b23 = bp[1];
    const uint64_t nb0 = pack_f32x2(-b01.x, -b01.y);
    const uint64_t nb1 = pack_f32x2(-b01.z, -b01.w);
    const uint64_t nb2 = pack_f32x2(-b23.x, -b23.y);
    const uint64_t nb3 = pack_f32x2(-b23.z, -b23.w);

    // Store base: out[g*P*P*T + i*P*T + j*T + t0]; per warp this is 512 B
    // contiguous (tid*16 B), perfectly coalesced STG.128.
    float* gout = out + (size_t)g * (PP * PP * TT) + (size_t)j * TT + t0
                + (size_t)i0 * (PP * TT);

    #pragma unroll 4
    for (int ii = 0; ii < IPB; ii++) {
        const int i = i0 + ii;

        const ulonglong2* ap = reinterpret_cast<const ulonglong2*>(&xs[i][t0]);
        ulonglong2 a01 = ap[0];   // .x=(x_t0,y_t0)  .y=(x_t0+1,y_t0+1)
        ulonglong2 a23 = ap[1];

        // Branchless diagonal: +1 under the sqrt when i==j, so
        // relu(THR - sqrt(0+1)) == 0 exactly (matches reference identity add).
        const float diag = (i == j) ? 1.0f : 0.0f;

        uint64_t d0 = f32x2_add(a01.x, nb0);
        uint64_t d1 = f32x2_add(a01.y, nb1);
        uint64_t d2 = f32x2_add(a23.x, nb2);
        uint64_t d3 = f32x2_add(a23.y, nb3);

        uint64_t s0 = f32x2_mul(d0, d0);
        uint64_t s1 = f32x2_mul(d1, d1);
        uint64_t s2 = f32x2_mul(d2, d2);
        uint64_t s3 = f32x2_mul(d3, d3);

        float2 q0 = unpack_f32x2(s0);
        float2 q1 = unpack_f32x2(s1);
        float2 q2 = unpack_f32x2(s2);
        float2 q3 = unpack_f32x2(s3);

        float4 v;
        v.x = fmaxf(0.0f, THRC - sqrt_approx(q0.x + q0.y + diag));
        v.y = fmaxf(0.0f, THRC - sqrt_approx(q1.x + q1.y + diag));
        v.z = fmaxf(0.0f, THRC - sqrt_approx(q2.x + q2.y + diag));
        v.w = fmaxf(0.0f, THRC - sqrt_approx(q3.x + q3.y + diag));

        // Streaming store: output is write-once, keep it out of L2's way.
        __stcs(reinterpret_cast<float4*>(gout + (size_t)ii * (PP * TT)), v);
    }
}

extern "C" void kernel_launch(void* const* d_in, const int* in_sizes, int n_in,
                              void* d_out, int out_size) {
    const float2* traj = (const float2*)d_in[0];  // trajectory (T, G*P, 2)
    float* out = (float*)d_out;                    // (G*P*P*T) fp32

    dim3 grid(ISPLIT, GG);
    traj_cost_kernel<<<grid, NTHREADS>>>(traj, out);
}